// round 11
// baseline (speedup 1.0000x reference)
#include <cuda_runtime.h>
#include <cstdint>
#include <cstddef>

#define B_ 1024
#define G_ 256
#define K_ 256
#define E_ 64
#define BETA_F 0.05f

// ---------------- scratch (__device__ globals: no runtime allocation) ----------
__device__ float gM [K_*E_*E_];    // 4 MB : M_k = W_k^T W_k
__device__ float gS6[K_*E_*E_];    // 4 MB : sum_{j=0..5} A^j
__device__ float gL [K_*E_*E_];    // 4 MB : chol(R_k), lower, upper zeroed
__device__ float gV [K_*E_];       // v_k = mu_k W_k
__device__ float gVL[K_*E_];       // vl_k = v_k L_k
__device__ float gMunorm[K_];
__device__ float gScore[B_*K_];    // 1 MB
__device__ int   gKmax[B_];
// X in mma-A-fragment layout, tf32 hi/lo: [bb=64][gg=32][lane=32][hi4 lo4]
__device__ float gXF[(size_t)64*32*32*8];          // 2 MB
// [WL_k | mu_k | 0pad] in mma-B-fragment layout: [k][gg=32][ni=9][lane=32][bh0,bh1,bl0,bl1]
__device__ float gWF[(size_t)K_*32*9*32*4];        // 37.75 MB

// ---------------- tf32 helpers -------------------------------------------------
__device__ __forceinline__ float tf32r(float x) {
    uint32_t r; asm("cvt.rna.tf32.f32 %0, %1;" : "=r"(r) : "f"(x));
    return __uint_as_float(r);
}
__device__ __forceinline__ void mma_tf32(float* c, const float* a, float b0, float b1) {
    asm volatile(
        "mma.sync.aligned.m16n8k8.row.col.f32.tf32.tf32.f32 "
        "{%0,%1,%2,%3},{%4,%5,%6,%7},{%8,%9},{%0,%1,%2,%3};"
        : "+f"(c[0]), "+f"(c[1]), "+f"(c[2]), "+f"(c[3])
        : "r"(__float_as_uint(a[0])), "r"(__float_as_uint(a[1])),
          "r"(__float_as_uint(a[2])), "r"(__float_as_uint(a[3])),
          "r"(__float_as_uint(b0)),  "r"(__float_as_uint(b1)));
}

// ---------------- K0: split X into a-fragment hi/lo layout (once) --------------
__global__ __launch_bounds__(256) void k0_xsplit(const float* __restrict__ X)
{
    int bb = blockIdx.x;           // 16-row block of B
    int t = threadIdx.x;
    __shared__ float Xs[16*260];
    for (int idx = t; idx < 4096; idx += 256) {
        int r = idx >> 8, c = idx & 255;
        Xs[r*260 + c] = X[(size_t)(bb*16 + r)*G_ + c];
    }
    __syncthreads();
    int lane = t & 31, wq = t >> 5;
    int gID = lane >> 2, tig = lane & 3;
#pragma unroll
    for (int q = 0; q < 4; q++) {
        int gg = wq*4 + q;
        int c0 = gg*8 + tig;
        float x0 = Xs[gID*260 + c0];
        float x1 = Xs[(gID+8)*260 + c0];
        float x2 = Xs[gID*260 + c0 + 4];
        float x3 = Xs[(gID+8)*260 + c0 + 4];
        float h0 = tf32r(x0), h1 = tf32r(x1), h2 = tf32r(x2), h3 = tf32r(x3);
        float* dst = gXF + ((size_t)(bb*32 + gg)*32 + lane)*8;
        *(float4*)dst       = make_float4(h0, h1, h2, h3);
        *(float4*)(dst + 4) = make_float4(tf32r(x0 - h0), tf32r(x1 - h1),
                                          tf32r(x2 - h2), tf32r(x3 - h3));
    }
}

// ---------------- K1: per-k  M, v, ||mu_k||^2 ----------------------------------
__global__ __launch_bounds__(256) void k1_prep(const float* __restrict__ mu,
                                               const float* __restrict__ w)
{
    int k = blockIdx.x;
    int t = threadIdx.x;
    __shared__ float Ws[64*64];
    __shared__ float mus[64];
    __shared__ float red[64];
    float acc[16];
#pragma unroll
    for (int i = 0; i < 16; i++) acc[i] = 0.f;
    float vacc = 0.f, mn = 0.f;
    const float* wk = w + (size_t)k * G_ * E_;
    for (int gc = 0; gc < G_; gc += 64) {
        const float* src = wk + (size_t)gc * E_;
        for (int idx = t; idx < 4096; idx += 256) Ws[idx] = src[idx];
        if (t < 64) mus[t] = mu[(size_t)(gc + t) * K_ + k];
        __syncthreads();
#pragma unroll
        for (int r = 0; r < 16; r++) {
            int idx = t + (r << 8);
            int e = idx >> 6, f = idx & 63;
            float a = 0.f;
#pragma unroll 16
            for (int g = 0; g < 64; g++) a += Ws[g*64 + e] * Ws[g*64 + f];
            acc[r] += a;
        }
        if (t < 64) {
            float va = 0.f;
#pragma unroll 16
            for (int g = 0; g < 64; g++) va += mus[g] * Ws[g*64 + t];
            vacc += va;
            mn += mus[t] * mus[t];
        }
        __syncthreads();
    }
    float* Mk = gM + (size_t)k * 4096;
#pragma unroll
    for (int r = 0; r < 16; r++) Mk[t + (r << 8)] = acc[r];
    if (t < 64) { gV[k*E_ + t] = vacc; red[t] = mn; }
    __syncthreads();
    if (t == 0) { float s = 0.f; for (int i = 0; i < 64; i++) s += red[i]; gMunorm[k] = s; }
}

// ---------------- K2a: per-k  S6, R, chol(R)=LL^T -> gL, vl --------------------
__global__ __launch_bounds__(256) void k2a_poly()
{
    int k = blockIdx.x;
    int t = threadIdx.x;
    __shared__ float Ms[64*64];
    __shared__ float Ss[64*64];
    const float* Mk = gM + (size_t)k * 4096;
    for (int idx = t; idx < 4096; idx += 256) {
        Ms[idx] = Mk[idx];
        Ss[idx] = ((idx >> 6) == (idx & 63)) ? 1.f : 0.f;
    }
    __syncthreads();
    for (int it = 0; it < 4; it++) {
        float val[16];
#pragma unroll
        for (int r = 0; r < 16; r++) {
            int idx = t + (r << 8);
            int e = idx >> 6, f = idx & 63;
            float a = 0.f;
#pragma unroll 16
            for (int g = 0; g < 64; g++) a += Ms[e*64 + g] * Ss[g*64 + f];
            float v = (1.f - BETA_F) * Ss[idx] - BETA_F * a;
            if (e == f) v += 1.f;
            val[r] = v;
        }
        __syncthreads();
#pragma unroll
        for (int r = 0; r < 16; r++) Ss[t + (r << 8)] = val[r];
        __syncthreads();
    }
    // Ss = S5. ms5 = M*S5 (regs); S6 -> gmem; Ms := ms5.
    float ms5[16];
#pragma unroll
    for (int r = 0; r < 16; r++) {
        int idx = t + (r << 8);
        int e = idx >> 6, f = idx & 63;
        float a = 0.f;
#pragma unroll 16
        for (int g = 0; g < 64; g++) a += Ms[e*64 + g] * Ss[g*64 + f];
        ms5[r] = a;
        float s6 = (1.f - BETA_F) * Ss[idx] - BETA_F * a;
        if (e == f) s6 += 1.f;
        gS6[(size_t)k*4096 + idx] = s6;
    }
    __syncthreads();
#pragma unroll
    for (int r = 0; r < 16; r++) Ms[t + (r << 8)] = ms5[r];
    __syncthreads();
    float rv[16];
#pragma unroll
    for (int r = 0; r < 16; r++) {
        int idx = t + (r << 8);
        int e = idx >> 6, f = idx & 63;
        float q = 0.f;
#pragma unroll 16
        for (int g = 0; g < 64; g++) q += Ms[e*64 + g] * Ss[g*64 + f];
        rv[r] = 2.f*BETA_F*Ss[idx] - BETA_F*BETA_F*q;
    }
    __syncthreads();
#pragma unroll
    for (int r = 0; r < 16; r++) Ss[t + (r << 8)] = rv[r];
    __syncthreads();

    // In-place Cholesky (lower) of Ss.
    for (int j = 0; j < 64; j++) {
        if (t == 0) Ss[j*65] = sqrtf(Ss[j*65]);
        __syncthreads();
        float dinv = __frcp_rn(Ss[j*65]);
        if (t > j && t < 64) Ss[t*64 + j] *= dinv;
        __syncthreads();
        for (int idx = t; idx < 4096; idx += 256) {
            int i = idx >> 6, c = idx & 63;
            if (c > j && c <= i) Ss[i*64 + c] -= Ss[i*64 + j] * Ss[c*64 + j];
        }
        __syncthreads();
    }
    for (int idx = t; idx < 4096; idx += 256) {
        int f = idx >> 6, e = idx & 63;
        if (f < e) Ss[idx] = 0.f;
    }
    __syncthreads();

    float* Lk = gL + (size_t)k*4096;
    for (int idx = t; idx < 4096; idx += 256) Lk[idx] = Ss[idx];

    if (t < 64) {   // vl = v * L
        float a = 0.f;
#pragma unroll 16
        for (int f = 0; f < 64; f++) a += gV[k*E_ + f] * Ss[f*64 + t];
        gVL[k*E_ + t] = a;
    }
}

// ---------------- K2b: WL = W*L chunk -> b-fragment hi/lo layout ---------------
// grid (4, 256): 64 g-rows x one k per block.
__global__ __launch_bounds__(256) void k2b_wfrag(const float* __restrict__ w,
                                                 const float* __restrict__ mu)
{
    int gc = blockIdx.x * 64;
    int k  = blockIdx.y;
    int t  = threadIdx.x;
    __shared__ float Ls[64*64];
    __shared__ float Ws[64*64];
    __shared__ float WLc[64*65];
    const float* Lk = gL + (size_t)k*4096;
    for (int idx = t; idx < 4096; idx += 256) Ls[idx] = Lk[idx];
    const float* src = w + ((size_t)k*G_ + gc)*E_;
    for (int idx = t; idx < 4096; idx += 256) Ws[idx] = src[idx];
    __syncthreads();
#pragma unroll
    for (int r = 0; r < 16; r++) {
        int idx = t + (r << 8);
        int g = idx >> 6, e = idx & 63;
        float a = 0.f;
#pragma unroll 16
        for (int f = 0; f < 64; f++) a += Ws[g*64 + f] * Ls[f*64 + e];
        WLc[g*65 + e] = a;
    }
    __syncthreads();
    int lane = t & 31, wq = t >> 5;
    int gID = lane >> 2, tig = lane & 3;
    int gg = (gc >> 3) + wq;       // global g8 group
    float* dstbase = gWF + ((size_t)k*32 + gg)*9*32*4;
#pragma unroll
    for (int ni = 0; ni < 9; ni++) {
        int col = ni*8 + gID;
        float v0, v1;
        if (ni < 8) {
            v0 = WLc[(wq*8 + tig)*65 + col];
            v1 = WLc[(wq*8 + tig + 4)*65 + col];
        } else {
            v0 = (gID == 0) ? mu[(size_t)(gc + wq*8 + tig)*K_ + k] : 0.f;
            v1 = (gID == 0) ? mu[(size_t)(gc + wq*8 + tig + 4)*K_ + k] : 0.f;
        }
        float h0 = tf32r(v0), h1 = tf32r(v1);
        *(float4*)(dstbase + (ni*32 + lane)*4) =
            make_float4(h0, h1, tf32r(v0 - h0), tf32r(v1 - h1));
    }
}

// ---------------- K3: frag-direct 3xTF32 GEMM + square-sum epilogue ------------
// grid (8, 256), 256 thr = 8 warps; warp w -> b16-block bb = blockIdx.x*8 + w.
// C = X * [WL_k | mu_k]; score_b = 2*C[b][64] + ||C[b][0:64]-vl_k||^2 - ||mu_k||^2
__global__ __launch_bounds__(256) void k3_score()
{
    const int k   = blockIdx.y;
    const int wq  = threadIdx.x >> 5, lane = threadIdx.x & 31;
    const int bb  = blockIdx.x*8 + wq;
    const int gID = lane >> 2, tig = lane & 3;

    float acc[9][4];
#pragma unroll
    for (int i = 0; i < 9; i++)
#pragma unroll
        for (int l = 0; l < 4; l++) acc[i][l] = 0.f;

    const float* xf = gXF + (size_t)bb*32*32*8;
    const float* wf = gWF + (size_t)k*32*9*32*4;

#pragma unroll 2
    for (int gg = 0; gg < 32; gg++) {
        float4 ah = __ldg((const float4*)(xf + ((size_t)gg*32 + lane)*8));
        float4 al = __ldg((const float4*)(xf + ((size_t)gg*32 + lane)*8 + 4));
        float a_h[4] = {ah.x, ah.y, ah.z, ah.w};
        float a_l[4] = {al.x, al.y, al.z, al.w};
#pragma unroll
        for (int ni = 0; ni < 9; ni++) {
            float4 bv = __ldg((const float4*)(wf + ((size_t)(gg*9 + ni)*32 + lane)*4));
            mma_tf32(acc[ni], a_h, bv.x, bv.y);   // hi*hi
            mma_tf32(acc[ni], a_h, bv.z, bv.w);   // hi*lo
            mma_tf32(acc[ni], a_l, bv.x, bv.y);   // lo*hi
        }
    }

    float p1 = 0.f, p2 = 0.f;
#pragma unroll
    for (int ni = 0; ni < 8; ni++) {
        int col = ni*8 + 2*tig;
        float v0 = gVL[k*E_ + col], v1 = gVL[k*E_ + col + 1];
        float d0 = acc[ni][0] - v0, d1 = acc[ni][1] - v1;
        float d2 = acc[ni][2] - v0, d3 = acc[ni][3] - v1;
        p1 += d0*d0 + d1*d1;
        p2 += d2*d2 + d3*d3;
    }
    p1 += __shfl_xor_sync(0xffffffffu, p1, 1);
    p1 += __shfl_xor_sync(0xffffffffu, p1, 2);
    p2 += __shfl_xor_sync(0xffffffffu, p2, 1);
    p2 += __shfl_xor_sync(0xffffffffu, p2, 2);

    if (tig == 0) {
        float mn = gMunorm[k];
        int r1 = bb*16 + gID;
        // acc[8][0]/acc[8][2] = C[r1][64]/C[r1+8][64] = x.mu (tig==0 lanes)
        gScore[(size_t)r1*K_ + k]     = 2.f*acc[8][0] + p1 - mn;
        gScore[(size_t)(r1+8)*K_ + k] = 2.f*acc[8][2] + p2 - mn;
    }
}

// ---------------- K4: argmax over k (first-max tie-break, like jnp.argmax) -----
__global__ __launch_bounds__(256) void k4_argmax()
{
    int b = blockIdx.x;
    int t = threadIdx.x;
    __shared__ float sv[256];
    __shared__ int   si[256];
    sv[t] = gScore[(size_t)b * K_ + t];
    si[t] = t;
    __syncthreads();
    for (int s = 128; s > 0; s >>= 1) {
        if (t < s) {
            float v2 = sv[t + s]; int i2 = si[t + s];
            if (v2 > sv[t] || (v2 == sv[t] && i2 < si[t])) { sv[t] = v2; si[t] = i2; }
        }
        __syncthreads();
    }
    if (t == 0) gKmax[b] = si[0];
}

// ---------------- K5: decode winner: y = beta*u*S6*W^T + mu_k ------------------
__global__ __launch_bounds__(256) void k5_decode(const float* __restrict__ X,
                                                 const float* __restrict__ mu,
                                                 const float* __restrict__ w,
                                                 float* __restrict__ y)
{
    int b = blockIdx.x;
    int t = threadIdx.x;
    __shared__ float upart[4][64];
    __shared__ float us[64];
    __shared__ float z6[64];
    int k = gKmax[b];
    const float* wk = w + (size_t)k * G_ * E_;

    {
        int e = t & 63, gq = t >> 6;
        float a = 0.f;
        const float* xb = X + (size_t)b * G_;
#pragma unroll 16
        for (int g = gq*64; g < gq*64 + 64; g++) a += xb[g] * wk[(size_t)g*E_ + e];
        upart[gq][e] = a;
    }
    __syncthreads();
    if (t < 64) us[t] = upart[0][t] + upart[1][t] + upart[2][t] + upart[3][t] - gV[k*E_ + t];
    __syncthreads();
    if (t < 64) {
        const float* S6k = gS6 + (size_t)k * 4096;
        float a = 0.f;
#pragma unroll 16
        for (int f = 0; f < 64; f++) a += us[f] * S6k[f*64 + t];
        z6[t] = BETA_F * a;
    }
    __syncthreads();
    {
        int g = t;
        float a = 0.f;
        const float* wg = wk + (size_t)g * E_;
#pragma unroll
        for (int e = 0; e < 64; e++) a += z6[e] * wg[e];
        y[(size_t)b * G_ + g] = a + mu[(size_t)g * K_ + k];
    }
}

// ---------------- launch --------------------------------------------------------
extern "C" void kernel_launch(void* const* d_in, const int* in_sizes, int n_in,
                              void* d_out, int out_size)
{
    const float* X  = (const float*)d_in[0];   // images (B,G)
    const float* mu = (const float*)d_in[1];   // (G,K)
    const float* w  = (const float*)d_in[2];   // (K,G,E)
    float* y = (float*)d_out;                  // (B,G)

    k0_xsplit<<<64, 256>>>(X);
    k1_prep<<<K_, 256>>>(mu, w);
    k2a_poly<<<K_, 256>>>();
    dim3 g2b(4, K_);
    k2b_wfrag<<<g2b, 256>>>(w, mu);
    dim3 g3(B_/128, K_);
    k3_score<<<g3, 256>>>();
    k4_argmax<<<B_, 256>>>();
    k5_decode<<<B_, 256>>>(X, mu, w, y);
}

// round 12
// speedup vs baseline: 1.6903x; 1.6903x over previous
#include <cuda_runtime.h>
#include <cstdint>
#include <cstddef>

#define B_ 1024
#define G_ 256
#define K_ 256
#define E_ 64
#define BETA_F 0.05f

// ---------------- scratch (__device__ globals: no runtime allocation) ----------
__device__ float gM [K_*E_*E_];   // 4 MB : M_k = W_k^T W_k
__device__ float gS6[K_*E_*E_];   // 4 MB : sum_{j=0..5} A^j
__device__ float gR [K_*E_*E_];   // 4 MB : 2b*S5 - b^2*S5*M*S5
__device__ float gV [K_*E_];      // v_k = mu_k W_k
__device__ float gMunorm[K_];
__device__ float gD2[B_*K_];      // 1 MB : 2*(x.mu_k) - ||mu_k||^2
__device__ float gScore[B_*K_];   // 1 MB
__device__ int   gKmax[B_];

// ---------------- cp.async helpers ---------------------------------------------
__device__ __forceinline__ void cp16(float* dst, const float* src) {
    uint32_t d = (uint32_t)__cvta_generic_to_shared(dst);
    asm volatile("cp.async.cg.shared.global [%0], [%1], 16;" :: "r"(d), "l"(src));
}
#define CP_COMMIT()  asm volatile("cp.async.commit_group;")
#define CP_WAIT(n)   asm volatile("cp.async.wait_group %0;" :: "n"(n))

// ---------------- K1: per-k  M, v, ||mu_k||^2 ----------------------------------
__global__ __launch_bounds__(256) void k1_prep(const float* __restrict__ mu,
                                               const float* __restrict__ w)
{
    int k = blockIdx.x;
    int t = threadIdx.x;
    __shared__ float Ws[64*64];
    __shared__ float mus[64];
    __shared__ float red[64];
    float acc[16];
#pragma unroll
    for (int i = 0; i < 16; i++) acc[i] = 0.f;
    float vacc = 0.f, mn = 0.f;
    const float* wk = w + (size_t)k * G_ * E_;
    for (int gc = 0; gc < G_; gc += 64) {
        const float* src = wk + (size_t)gc * E_;
        for (int idx = t; idx < 4096; idx += 256) Ws[idx] = src[idx];
        if (t < 64) mus[t] = mu[(size_t)(gc + t) * K_ + k];
        __syncthreads();
#pragma unroll
        for (int r = 0; r < 16; r++) {
            int idx = t + (r << 8);
            int e = idx >> 6, f = idx & 63;
            float a = 0.f;
#pragma unroll 16
            for (int g = 0; g < 64; g++) a += Ws[g*64 + e] * Ws[g*64 + f];
            acc[r] += a;
        }
        if (t < 64) {
            float va = 0.f;
#pragma unroll 16
            for (int g = 0; g < 64; g++) va += mus[g] * Ws[g*64 + t];
            vacc += va;
            mn += mus[t] * mus[t];
        }
        __syncthreads();
    }
    float* Mk = gM + (size_t)k * 4096;
#pragma unroll
    for (int r = 0; r < 16; r++) Mk[t + (r << 8)] = acc[r];
    if (t < 64) { gV[k*E_ + t] = vacc; red[t] = mn; }
    __syncthreads();
    if (t == 0) { float s = 0.f; for (int i = 0; i < 64; i++) s += red[i]; gMunorm[k] = s; }
}

// ---------------- K2: per-k  S6 and R ------------------------------------------
__global__ __launch_bounds__(256) void k2_poly()
{
    int k = blockIdx.x;
    int t = threadIdx.x;
    __shared__ float Ms[64*64];
    __shared__ float Ss[64*64];
    const float* Mk = gM + (size_t)k * 4096;
    for (int idx = t; idx < 4096; idx += 256) {
        Ms[idx] = Mk[idx];
        Ss[idx] = ((idx >> 6) == (idx & 63)) ? 1.f : 0.f;
    }
    __syncthreads();
    for (int it = 0; it < 4; it++) {
        float val[16];
#pragma unroll
        for (int r = 0; r < 16; r++) {
            int idx = t + (r << 8);
            int e = idx >> 6, f = idx & 63;
            float a = 0.f;
#pragma unroll 16
            for (int g = 0; g < 64; g++) a += Ms[e*64 + g] * Ss[g*64 + f];
            float v = (1.f - BETA_F) * Ss[idx] - BETA_F * a;
            if (e == f) v += 1.f;
            val[r] = v;
        }
        __syncthreads();
#pragma unroll
        for (int r = 0; r < 16; r++) Ss[t + (r << 8)] = val[r];
        __syncthreads();
    }
    float ms5[16];
#pragma unroll
    for (int r = 0; r < 16; r++) {
        int idx = t + (r << 8);
        int e = idx >> 6, f = idx & 63;
        float a = 0.f;
#pragma unroll 16
        for (int g = 0; g < 64; g++) a += Ms[e*64 + g] * Ss[g*64 + f];
        ms5[r] = a;
        float s6 = (1.f - BETA_F) * Ss[idx] - BETA_F * a;
        if (e == f) s6 += 1.f;
        gS6[(size_t)k*4096 + idx] = s6;
    }
    __syncthreads();
#pragma unroll
    for (int r = 0; r < 16; r++) Ms[t + (r << 8)] = ms5[r];
    __syncthreads();
#pragma unroll
    for (int r = 0; r < 16; r++) {
        int idx = t + (r << 8);
        int e = idx >> 6, f = idx & 63;
        float q = 0.f;
#pragma unroll 16
        for (int g = 0; g < 64; g++) q += Ms[e*64 + g] * Ss[g*64 + f];
        gR[(size_t)k*4096 + idx] = 2.f*BETA_F*Ss[idx] - BETA_F*BETA_F*q;
    }
}

// ---------------- KD: gD2[b][k] = 2*(x_b.mu_k) - ||mu_k||^2 --------------------
// grid (16, 4): 64 b x 64 k tile, 256 thr, 4x4 micro.
__global__ __launch_bounds__(256) void kD_dots(const float* __restrict__ X,
                                               const float* __restrict__ mu)
{
    const int b0 = blockIdx.x * 64;
    const int kc = blockIdx.y * 64;
    const int t  = threadIdx.x;
    const int tx = t & 15;   // k-group
    const int ty = t >> 4;   // b-group
    __shared__ float XsT[32*68];   // [j][b]
    __shared__ float Ms[32*64];    // [j][k]
    float acc[4][4];
#pragma unroll
    for (int i = 0; i < 4; i++)
#pragma unroll
        for (int l = 0; l < 4; l++) acc[i][l] = 0.f;

    for (int gc = 0; gc < G_; gc += 32) {
        for (int idx = t; idx < 2048; idx += 256) {
            int i = idx >> 5, j = idx & 31;
            XsT[j*68 + i] = X[(size_t)(b0 + i)*G_ + gc + j];
        }
        for (int idx = t; idx < 2048; idx += 256) {
            int j = idx >> 6, e = idx & 63;
            Ms[idx] = mu[(size_t)(gc + j)*K_ + kc + e];
        }
        __syncthreads();
#pragma unroll
        for (int j = 0; j < 32; j++) {
            float4 a = *(const float4*)&XsT[j*68 + ty*4];
            float4 m = *(const float4*)&Ms [j*64 + tx*4];
            acc[0][0] += a.x*m.x; acc[0][1] += a.x*m.y; acc[0][2] += a.x*m.z; acc[0][3] += a.x*m.w;
            acc[1][0] += a.y*m.x; acc[1][1] += a.y*m.y; acc[1][2] += a.y*m.z; acc[1][3] += a.y*m.w;
            acc[2][0] += a.z*m.x; acc[2][1] += a.z*m.y; acc[2][2] += a.z*m.z; acc[2][3] += a.z*m.w;
            acc[3][0] += a.w*m.x; acc[3][1] += a.w*m.y; acc[3][2] += a.w*m.z; acc[3][3] += a.w*m.w;
        }
        __syncthreads();
    }
#pragma unroll
    for (int i = 0; i < 4; i++)
#pragma unroll
        for (int l = 0; l < 4; l++) {
            int kk = kc + tx*4 + l;
            gD2[(size_t)(b0 + ty*4 + i)*K_ + kk] = 2.f*acc[i][l] - gMunorm[kk];
        }
}

// ---------------- K3: double-buffered mainloop, 128 b x 2 k per block ----------
// score_{b,k} = gD2[b][k] + u R_k u^T, u = x_b W_k - v_k.
// 256 thr: tx = e-group (16x4), ty = b-group (16x8). cp.async pipeline depth 2.
// dyn smem: 2 x (Xs[128][36] + Ws0[32*64] + Ws1[32*64]) = 17408 floats,
// reused as UsT0[64*132] + UsT1[64*132] + Rs[64*64]; + qpart[128].
__global__ __launch_bounds__(256) void k3_score(const float* __restrict__ X,
                                                const float* __restrict__ w)
{
    extern __shared__ float S[];
    const int k0 = blockIdx.y * 2;
    const int b0 = blockIdx.x * 128;
    const int t  = threadIdx.x;
    const int tx = t & 15;
    const int ty = t >> 4;

    float u0[8][4], u1[8][4];
#pragma unroll
    for (int i = 0; i < 8; i++)
#pragma unroll
        for (int l = 0; l < 4; l++) { u0[i][l] = 0.f; u1[i][l] = 0.f; }

    const float* wk0 = w + (size_t)k0 * G_ * E_;
    const float* wk1 = wk0 + (size_t)G_ * E_;

    // ---- issue tile gi into buffer gi&1 ----
    auto issue = [&](int gi) {
        float* xb  = S + (gi & 1) * 8704;
        float* wb0 = xb + 4608;
        float* wb1 = wb0 + 2048;
        int gc = gi * 32;
#pragma unroll
        for (int s = 0; s < 4; s++) {
            int idx = t + s*256;           // 1024 chunks: 128 rows x 8
            int row = idx >> 3, ch = (idx & 7) << 2;
            cp16(&xb[row*36 + ch], &X[(size_t)(b0 + row)*G_ + gc + ch]);
        }
#pragma unroll
        for (int s = 0; s < 2; s++) {
            int idx = (t + s*256) << 2;    // 512 chunks each
            cp16(&wb0[idx], &wk0[(size_t)gc*E_ + idx]);
            cp16(&wb1[idx], &wk1[(size_t)gc*E_ + idx]);
        }
    };

    issue(0); CP_COMMIT();
    for (int gi = 0; gi < 8; gi++) {
        if (gi < 7) { issue(gi + 1); CP_COMMIT(); CP_WAIT(1); }
        else        { CP_WAIT(0); }
        __syncthreads();
        float* xb  = S + (gi & 1) * 8704;
        float* wb0 = xb + 4608;
        float* wb1 = wb0 + 2048;
#pragma unroll
        for (int j = 0; j < 32; j++) {
            float a[8];
#pragma unroll
            for (int i = 0; i < 8; i++) a[i] = xb[(ty*8 + i)*36 + j];
            float4 w0 = *(const float4*)&wb0[j*64 + tx*4];
            float4 w1 = *(const float4*)&wb1[j*64 + tx*4];
#pragma unroll
            for (int i = 0; i < 8; i++) {
                u0[i][0] += a[i]*w0.x; u0[i][1] += a[i]*w0.y;
                u0[i][2] += a[i]*w0.z; u0[i][3] += a[i]*w0.w;
                u1[i][0] += a[i]*w1.x; u1[i][1] += a[i]*w1.y;
                u1[i][2] += a[i]*w1.z; u1[i][3] += a[i]*w1.w;
            }
        }
        __syncthreads();
    }

    // ---- stage u = C - v into UsT[e][b] for both k ----
    float* UsT0 = S;
    float* UsT1 = S + 8448;
    float* Rs   = S + 16896;
    float* qp   = S + 20992;
    {
        const float4 v0 = *(const float4*)&gV[k0*E_ + tx*4];
        const float4 v1 = *(const float4*)&gV[(k0+1)*E_ + tx*4];
#pragma unroll
        for (int i = 0; i < 8; i++) {
            int b = ty*8 + i;
            UsT0[(tx*4+0)*132 + b] = u0[i][0] - v0.x;
            UsT0[(tx*4+1)*132 + b] = u0[i][1] - v0.y;
            UsT0[(tx*4+2)*132 + b] = u0[i][2] - v0.z;
            UsT0[(tx*4+3)*132 + b] = u0[i][3] - v0.w;
            UsT1[(tx*4+0)*132 + b] = u1[i][0] - v1.x;
            UsT1[(tx*4+1)*132 + b] = u1[i][1] - v1.y;
            UsT1[(tx*4+2)*132 + b] = u1[i][2] - v1.z;
            UsT1[(tx*4+3)*132 + b] = u1[i][3] - v1.w;
        }
    }
    __syncthreads();

    // ---- quadform per k: T = U*R; p_b = sum_e T[b][e]*U[b][e] ----
#pragma unroll 1
    for (int kk = 0; kk < 2; kk++) {
        const float* ust = kk ? UsT1 : UsT0;
        const float* Rk = gR + (size_t)(k0 + kk) * 4096;
#pragma unroll
        for (int s = 0; s < 4; s++) {
            int idx = (t + s*256) << 2;
            cp16(&Rs[idx], &Rk[idx]);
        }
        CP_COMMIT(); CP_WAIT(0);
        __syncthreads();

        float tacc[8][4];
#pragma unroll
        for (int i = 0; i < 8; i++)
#pragma unroll
            for (int l = 0; l < 4; l++) tacc[i][l] = 0.f;
#pragma unroll 8
        for (int f = 0; f < 64; f++) {
            float4 a0 = *(const float4*)&ust[f*132 + ty*8];
            float4 a1 = *(const float4*)&ust[f*132 + ty*8 + 4];
            float4 rr = *(const float4*)&Rs[f*64 + tx*4];
            tacc[0][0] += a0.x*rr.x; tacc[0][1] += a0.x*rr.y; tacc[0][2] += a0.x*rr.z; tacc[0][3] += a0.x*rr.w;
            tacc[1][0] += a0.y*rr.x; tacc[1][1] += a0.y*rr.y; tacc[1][2] += a0.y*rr.z; tacc[1][3] += a0.y*rr.w;
            tacc[2][0] += a0.z*rr.x; tacc[2][1] += a0.z*rr.y; tacc[2][2] += a0.z*rr.z; tacc[2][3] += a0.z*rr.w;
            tacc[3][0] += a0.w*rr.x; tacc[3][1] += a0.w*rr.y; tacc[3][2] += a0.w*rr.z; tacc[3][3] += a0.w*rr.w;
            tacc[4][0] += a1.x*rr.x; tacc[4][1] += a1.x*rr.y; tacc[4][2] += a1.x*rr.z; tacc[4][3] += a1.x*rr.w;
            tacc[5][0] += a1.y*rr.x; tacc[5][1] += a1.y*rr.y; tacc[5][2] += a1.y*rr.z; tacc[5][3] += a1.y*rr.w;
            tacc[6][0] += a1.z*rr.x; tacc[6][1] += a1.z*rr.y; tacc[6][2] += a1.z*rr.z; tacc[6][3] += a1.z*rr.w;
            tacc[7][0] += a1.w*rr.x; tacc[7][1] += a1.w*rr.y; tacc[7][2] += a1.w*rr.z; tacc[7][3] += a1.w*rr.w;
        }
        float p[8];
#pragma unroll
        for (int i = 0; i < 8; i++) p[i] = 0.f;
#pragma unroll
        for (int l = 0; l < 4; l++) {
            float4 uu0 = *(const float4*)&ust[(tx*4+l)*132 + ty*8];
            float4 uu1 = *(const float4*)&ust[(tx*4+l)*132 + ty*8 + 4];
            p[0] += tacc[0][l]*uu0.x; p[1] += tacc[1][l]*uu0.y;
            p[2] += tacc[2][l]*uu0.z; p[3] += tacc[3][l]*uu0.w;
            p[4] += tacc[4][l]*uu1.x; p[5] += tacc[5][l]*uu1.y;
            p[6] += tacc[6][l]*uu1.z; p[7] += tacc[7][l]*uu1.w;
        }
#pragma unroll
        for (int i = 0; i < 8; i++) {
#pragma unroll
            for (int ofs = 8; ofs > 0; ofs >>= 1)
                p[i] += __shfl_down_sync(0xffffffffu, p[i], ofs, 16);
        }
        if (tx == 0) {
#pragma unroll
            for (int i = 0; i < 8; i++) qp[ty*8 + i] = p[i];
        }
        __syncthreads();
        if (t < 128) {
            int k = k0 + kk;
            gScore[(size_t)(b0 + t)*K_ + k] = gD2[(size_t)(b0 + t)*K_ + k] + qp[t];
        }
        __syncthreads();
    }
}

// ---------------- K4: argmax over k (first-max tie-break, like jnp.argmax) -----
__global__ __launch_bounds__(256) void k4_argmax()
{
    int b = blockIdx.x;
    int t = threadIdx.x;
    __shared__ float sv[256];
    __shared__ int   si[256];
    sv[t] = gScore[(size_t)b * K_ + t];
    si[t] = t;
    __syncthreads();
    for (int s = 128; s > 0; s >>= 1) {
        if (t < s) {
            float v2 = sv[t + s]; int i2 = si[t + s];
            if (v2 > sv[t] || (v2 == sv[t] && i2 < si[t])) { sv[t] = v2; si[t] = i2; }
        }
        __syncthreads();
    }
    if (t == 0) gKmax[b] = si[0];
}

// ---------------- K5: decode winner: y = beta*u*S6*W^T + mu_k ------------------
__global__ __launch_bounds__(256) void k5_decode(const float* __restrict__ X,
                                                 const float* __restrict__ mu,
                                                 const float* __restrict__ w,
                                                 float* __restrict__ y)
{
    int b = blockIdx.x;
    int t = threadIdx.x;
    __shared__ float upart[4][64];
    __shared__ float us[64];
    __shared__ float z6[64];
    int k = gKmax[b];
    const float* wk = w + (size_t)k * G_ * E_;

    {
        int e = t & 63, gq = t >> 6;
        float a = 0.f;
        const float* xb = X + (size_t)b * G_;
#pragma unroll 16
        for (int g = gq*64; g < gq*64 + 64; g++) a += xb[g] * wk[(size_t)g*E_ + e];
        upart[gq][e] = a;
    }
    __syncthreads();
    if (t < 64) us[t] = upart[0][t] + upart[1][t] + upart[2][t] + upart[3][t] - gV[k*E_ + t];
    __syncthreads();
    if (t < 64) {
        const float* S6k = gS6 + (size_t)k * 4096;
        float a = 0.f;
#pragma unroll 16
        for (int f = 0; f < 64; f++) a += us[f] * S6k[f*64 + t];
        z6[t] = BETA_F * a;
    }
    __syncthreads();
    {
        int g = t;
        float a = 0.f;
        const float* wg = wk + (size_t)g * E_;
#pragma unroll
        for (int e = 0; e < 64; e++) a += z6[e] * wg[e];
        y[(size_t)b * G_ + g] = a + mu[(size_t)g * K_ + k];
    }
}

// ---------------- launch --------------------------------------------------------
extern "C" void kernel_launch(void* const* d_in, const int* in_sizes, int n_in,
                              void* d_out, int out_size)
{
    const float* X  = (const float*)d_in[0];   // images (B,G)
    const float* mu = (const float*)d_in[1];   // (G,K)
    const float* w  = (const float*)d_in[2];   // (K,G,E)
    float* y = (float*)d_out;                  // (B,G)

    const int smem3 = 21120 * 4;   // 84480 B dynamic smem for k3
    cudaFuncSetAttribute(k3_score, cudaFuncAttributeMaxDynamicSharedMemorySize, smem3);

    k1_prep<<<K_, 256>>>(mu, w);
    k2_poly<<<K_, 256>>>();
    dim3 gD(B_/64, K_/64);
    kD_dots<<<gD, 256>>>(X, mu);
    dim3 g3(B_/128, K_/2);
    k3_score<<<g3, 256, smem3>>>(X, w);
    k4_argmax<<<B_, 256>>>();
    k5_decode<<<B_, 256>>>(X, mu, w, y);
}